// round 12
// baseline (speedup 1.0000x reference)
#include <cuda_runtime.h>
#include <cuda_bf16.h>
#include <cstdint>

typedef unsigned long long u64;

#define NSMAX 131072
__device__ float g_c1[108 * NSMAX];   // conv1+pool output [ch*36+y*6+x][sample]
__device__ float g_p2[54 * NSMAX];    // conv2+pool output [k][sample]

__device__ __forceinline__ u64 dup2(float a) {
    u64 r; asm("mov.b64 %0, {%1, %1};" : "=l"(r) : "r"(__float_as_uint(a))); return r;
}
__device__ __forceinline__ u64 pack2(float lo, float hi) {
    u64 r; asm("mov.b64 %0, {%1, %2};" : "=l"(r) : "r"(__float_as_uint(lo)), "r"(__float_as_uint(hi))); return r;
}
__device__ __forceinline__ void fma2(u64& acc, u64 a, u64 b) {
    asm("fma.rn.f32x2 %0, %1, %2, %0;" : "+l"(acc) : "l"(a), "l"(b));
}
__device__ __forceinline__ float2 unpack2(u64 v) {
    unsigned lo, hi; asm("mov.b64 {%0, %1}, %2;" : "=r"(lo), "=r"(hi) : "l"(v));
    return make_float2(__uint_as_float(lo), __uint_as_float(hi));
}

// ================================================================
// Kernel A1: conv1 (1->3, 3x3 pad1, 12x12) + maxpool2 + relu -> g_c1
// 128 thr / 128 samples; x staged in smem (stride 129, conflict-free reads)
// ================================================================
#define A1TPB 128
#define A1_XS 129
#define A1_SMEM (128 * A1_XS * 4)

__global__ void __launch_bounds__(A1TPB, 3)
conv1_kernel(const float* __restrict__ x,
             const float* __restrict__ c1w, const float* __restrict__ c1b, int nsamp)
{
    extern __shared__ float sx[];
    __shared__ float ws[32];
    const int tid = threadIdx.x;
    if (tid < 27) ws[tid] = c1w[tid];
    if (tid < 3)  ws[27 + tid] = c1b[tid];

    const long long base = (long long)blockIdx.x * A1TPB;

    // coalesced stage: x[base+row][q*4..q*4+3] -> sx[row*129 + ...]
    for (int i = tid; i < 128 * 32; i += A1TPB) {
        const int row = i >> 5, q = (i & 31) * 4;
        const long long s = base + row;
        float4 v = make_float4(0.f, 0.f, 0.f, 0.f);
        if (s < nsamp) v = *(const float4*)(x + s * 128 + q);
        float* d = sx + row * A1_XS + q;
        d[0] = v.x; d[1] = v.y; d[2] = v.z; d[3] = v.w;
    }
    __syncthreads();

    const long long s = base + tid;
    if (s >= nsamp) return;
    const float* xp = sx + tid * A1_XS;

    float W[27];
#pragma unroll
    for (int i = 0; i < 27; i++) W[i] = ws[i];
    const float B0 = ws[27], B1 = ws[28], B2 = ws[29];

#pragma unroll
    for (int py = 0; py < 6; py++) {
        float r[4][12];
#pragma unroll
        for (int j = 0; j < 4; j++) {
            const int rr = 2 * py - 1 + j;
            if (rr < 0 || rr >= 11) {
#pragma unroll
                for (int c = 0; c < 12; c++) r[j][c] = 0.0f;
            } else if (rr == 10) {
#pragma unroll
                for (int c = 0; c < 8; c++) r[j][c] = xp[120 + c];
                r[j][8] = 0.0f; r[j][9] = 0.0f; r[j][10] = 0.0f; r[j][11] = 0.0f;
            } else {
#pragma unroll
                for (int c = 0; c < 12; c++) r[j][c] = xp[12 * rr + c];
            }
        }
#pragma unroll
        for (int oc = 0; oc < 3; oc++) {
            float v0[12], v1[12];
#pragma unroll
            for (int cx = 0; cx < 12; cx++) {
                float a0 = 0.0f, a1 = 0.0f;
#pragma unroll
                for (int ky = 0; ky < 3; ky++) {
#pragma unroll
                    for (int kx = 0; kx < 3; kx++) {
                        const int col = cx + kx - 1;
                        if (col >= 0 && col < 12) {
                            const float w = W[oc * 9 + ky * 3 + kx];
                            a0 = fmaf(w, r[ky][col],     a0);
                            a1 = fmaf(w, r[ky + 1][col], a1);
                        }
                    }
                }
                v0[cx] = a0; v1[cx] = a1;
            }
            const float bb = (oc == 0) ? B0 : ((oc == 1) ? B1 : B2);
#pragma unroll
            for (int px = 0; px < 6; px++) {
                float m = fmaxf(fmaxf(v0[2 * px], v0[2 * px + 1]),
                                fmaxf(v1[2 * px], v1[2 * px + 1]));
                g_c1[(long long)(oc * 36 + py * 6 + px) * NSMAX + s] = fmaxf(m + bb, 0.0f);
            }
        }
    }
}

// ================================================================
// Kernel A2: conv2 (3->6, 3x3 pad1, 6x6) + maxpool2 + relu -> g_p2
// 128 thr; all 6 oc per pass -> single rw window load per (py, ic)
// ================================================================
#define A2TPB 128
__global__ void __launch_bounds__(A2TPB)
conv2_kernel(const float* __restrict__ c2w, const float* __restrict__ c2b, int nsamp)
{
    __shared__ float ws[168];
    const int tid = threadIdx.x;
    for (int i = tid; i < 162; i += A2TPB) ws[i] = c2w[i];
    for (int i = tid; i < 6;   i += A2TPB) ws[162 + i] = c2b[i];
    __syncthreads();

    const long long s = (long long)blockIdx.x * A2TPB + tid;
    if (s >= nsamp) return;

#pragma unroll
    for (int py = 0; py < 3; py++) {
        u64 acc[6][3][2];
#pragma unroll
        for (int oc = 0; oc < 6; oc++)
#pragma unroll
            for (int px = 0; px < 3; px++) { acc[oc][px][0] = 0ull; acc[oc][px][1] = 0ull; }

#pragma unroll
        for (int ic = 0; ic < 3; ic++) {
            float rw[4][6];
#pragma unroll
            for (int j = 0; j < 4; j++) {
                const int y = 2 * py - 1 + j;
                if (y < 0 || y > 5) {
#pragma unroll
                    for (int ix = 0; ix < 6; ix++) rw[j][ix] = 0.0f;
                } else {
#pragma unroll
                    for (int ix = 0; ix < 6; ix++)
                        rw[j][ix] = g_c1[(long long)(ic * 36 + y * 6 + ix) * NSMAX + s];
                }
            }
            u64 pc[3][6];
#pragma unroll
            for (int j = 0; j < 3; j++)
#pragma unroll
                for (int ix = 0; ix < 6; ix++)
                    pc[j][ix] = pack2(rw[j][ix], rw[j + 1][ix]);

#pragma unroll
            for (int oc = 0; oc < 6; oc++) {
#pragma unroll
                for (int ky = 0; ky < 3; ky++) {
#pragma unroll
                    for (int kx = 0; kx < 3; kx++) {
                        const u64 wd = dup2(ws[oc * 27 + ic * 9 + ky * 3 + kx]);
#pragma unroll
                        for (int px = 0; px < 3; px++) {
                            const int ix0 = 2 * px + kx - 1;
                            const int ix1 = 2 * px + kx;
                            if (ix0 >= 0 && ix0 < 6) fma2(acc[oc][px][0], wd, pc[ky][ix0]);
                            if (ix1 < 6)             fma2(acc[oc][px][1], wd, pc[ky][ix1]);
                        }
                    }
                }
            }
        }
#pragma unroll
        for (int oc = 0; oc < 6; oc++) {
            const float bb = ws[162 + oc];
#pragma unroll
            for (int px = 0; px < 3; px++) {
                float2 v0 = unpack2(acc[oc][px][0]), v1 = unpack2(acc[oc][px][1]);
                float m = fmaxf(fmaxf(v0.x, v0.y), fmaxf(v1.x, v1.y));
                g_p2[(long long)(oc * 9 + py * 3 + px) * NSMAX + s] = fmaxf(m + bb, 0.0f);
            }
        }
    }
}

// ================================================================
// Kernel F: fused fc1+relu+out via chained mma.sync bf16 3-term split
// (unchanged from round 11 — passing)
// ================================================================
#define FK_TPB  512
#define F_B1   0
#define F_B2   512
#define F_W1H  1024
#define F_W1L  19456
#define F_W2H  37888
#define F_W2L  72704
#define F_P2H  107520
#define F_P2L  125952
#define F_HH   144384
#define F_HL   179200
#define F_D    144384
#define FK_SMEM 214016

#define LDSM_X4(r0, r1, r2, r3, addr) \
    asm volatile("ldmatrix.sync.aligned.m8n8.x4.shared.b16 {%0,%1,%2,%3}, [%4];" \
        : "=r"(r0), "=r"(r1), "=r"(r2), "=r"(r3) : "r"(addr))

#define MMA_BF16(c, a, b0, b1) \
    asm volatile("mma.sync.aligned.m16n8k16.row.col.f32.bf16.bf16.f32 " \
        "{%0,%1,%2,%3}, {%4,%5,%6,%7}, {%8,%9}, {%0,%1,%2,%3};" \
        : "+f"((c)[0]), "+f"((c)[1]), "+f"((c)[2]), "+f"((c)[3]) \
        : "r"((a)[0]), "r"((a)[1]), "r"((a)[2]), "r"((a)[3]), "r"(b0), "r"(b1))

__device__ __forceinline__ uint32_t smem_u32(const void* p) {
    uint32_t a;
    asm("{ .reg .u64 t; cvta.to.shared.u64 t, %1; cvt.u32.u64 %0, t; }" : "=r"(a) : "l"(p));
    return a;
}
__device__ __forceinline__ void bf16split(float f0, float f1, unsigned& hi, unsigned& lo) {
    asm("cvt.rn.bf16x2.f32 %0, %1, %2;" : "=r"(hi) : "f"(f1), "f"(f0));
    const float h0 = __uint_as_float(hi << 16);
    const float h1 = __uint_as_float(hi & 0xFFFF0000u);
    const float r0 = f0 - h0, r1 = f1 - h1;
    asm("cvt.rn.bf16x2.f32 %0, %1, %2;" : "=r"(lo) : "f"(r1), "f"(r0));
}
__device__ __forceinline__ void bf16split1(float v, unsigned short& hi, unsigned short& lo) {
    __nv_bfloat16 h = __float2bfloat16(v);
    float r = v - __bfloat162float(h);
    __nv_bfloat16 l = __float2bfloat16(r);
    hi = *(unsigned short*)&h;
    lo = *(unsigned short*)&l;
}

__global__ void __launch_bounds__(FK_TPB, 1)
head_kernel(const float* __restrict__ w1, const float* __restrict__ b1,
            const float* __restrict__ w2, const float* __restrict__ b2,
            float* __restrict__ out, int nsamp, int ntiles)
{
    extern __shared__ char smem[];
    const uint32_t sb = smem_u32(smem);
    const int tid = threadIdx.x;
    const int wid = tid >> 5, lid = tid & 31;

    if (tid < 128) { ((float*)(smem + F_B1))[tid] = b1[tid];
                     ((float*)(smem + F_B2))[tid] = b2[tid]; }
    for (int i = tid; i < (18432 * 4) / 4; i += FK_TPB)
        ((uint32_t*)(smem + F_W1H))[i] = 0u;
    for (int i = tid; i < 18432 / 4; i += FK_TPB) {
        ((uint32_t*)(smem + F_P2H))[i] = 0u;
        ((uint32_t*)(smem + F_P2L))[i] = 0u;
    }
    __syncthreads();
    if (tid < 128) {
        const int o = tid;
        const float* wr = w1 + o * 54;
        char* ah = smem + F_W1H + o * 144;
        char* al = smem + F_W1L + o * 144;
        for (int i = 0; i < 54; i += 2) {
            const float2 f = *(const float2*)(wr + i);
            unsigned h, l;
            bf16split(f.x, f.y, h, l);
            *(unsigned*)(ah + i * 2) = h;
            *(unsigned*)(al + i * 2) = l;
        }
    }
    {
        const int o  = tid & 127;
        const int kq = (tid >> 7) * 32;
        const float* wr = w2 + o * 128 + kq;
        char* ah = smem + F_W2H + o * 272 + kq * 2;
        char* al = smem + F_W2L + o * 272 + kq * 2;
        for (int i = 0; i < 32; i += 4) {
            const float4 f = *(const float4*)(wr + i);
            unsigned h0, l0, h1, l1;
            bf16split(f.x, f.y, h0, l0);
            bf16split(f.z, f.w, h1, l1);
            *(uint2*)(ah + i * 2) = make_uint2(h0, h1);
            *(uint2*)(al + i * 2) = make_uint2(l0, l1);
        }
    }

    const int mgrp = wid & 3;
    const int ngrp = wid >> 2;
    const int mbase0 = mgrp * 32;
    const int nbase  = ngrp * 32;
    const uint32_t ar = (uint32_t)((lid & 7) + 8 * ((lid >> 3) & 1));
    const uint32_t bq = (uint32_t)((lid & 7) + 8 * (lid >> 4));
    const int mo = lid >> 2;
    const int no = 2 * (lid & 3);

    for (int tile = blockIdx.x; tile < ntiles; tile += gridDim.x) {
        const long long tbase = (long long)tile * 128;

        __syncthreads();

        for (int idx = tid; idx < 54 * 32; idx += FK_TPB) {
            const int k = idx >> 5, s4 = (idx & 31) * 4;
            const float4 f = *(const float4*)(g_p2 + (long long)k * NSMAX + tbase + s4);
            unsigned short h, l;
#pragma unroll
            for (int j = 0; j < 4; j++) {
                const float v = (j == 0) ? f.x : (j == 1) ? f.y : (j == 2) ? f.z : f.w;
                bf16split1(v, h, l);
                *(unsigned short*)(smem + F_P2H + (s4 + j) * 144 + k * 2) = h;
                *(unsigned short*)(smem + F_P2L + (s4 + j) * 144 + k * 2) = l;
            }
        }
        __syncthreads();

        float acc1[2][4][4];
#pragma unroll
        for (int mt = 0; mt < 2; mt++)
#pragma unroll
            for (int nt = 0; nt < 4; nt++)
#pragma unroll
                for (int q = 0; q < 4; q++) acc1[mt][nt][q] = 0.0f;

#pragma unroll
        for (int k0 = 0; k0 < 64; k0 += 16) {
            const uint32_t ac = (uint32_t)(k0 + 8 * (lid >> 4));
            uint32_t ahi[2][4], alo[2][4];
#pragma unroll
            for (int mt = 0; mt < 2; mt++) {
                const uint32_t off = (mbase0 + mt * 16 + ar) * 144 + ac * 2;
                LDSM_X4(ahi[mt][0], ahi[mt][1], ahi[mt][2], ahi[mt][3], sb + F_W1H + off);
                LDSM_X4(alo[mt][0], alo[mt][1], alo[mt][2], alo[mt][3], sb + F_W1L + off);
            }
            const uint32_t bc = (uint32_t)(k0 + 8 * ((lid >> 3) & 1));
#pragma unroll
            for (int np = 0; np < 2; np++) {
                const uint32_t off = (nbase + np * 16 + bq) * 144 + bc * 2;
                uint32_t bh[4], bl[4];
                LDSM_X4(bh[0], bh[1], bh[2], bh[3], sb + F_P2H + off);
                LDSM_X4(bl[0], bl[1], bl[2], bl[3], sb + F_P2L + off);
#pragma unroll
                for (int mt = 0; mt < 2; mt++) {
                    MMA_BF16(acc1[mt][2 * np],     ahi[mt], bh[0], bh[1]);
                    MMA_BF16(acc1[mt][2 * np],     ahi[mt], bl[0], bl[1]);
                    MMA_BF16(acc1[mt][2 * np],     alo[mt], bh[0], bh[1]);
                    MMA_BF16(acc1[mt][2 * np + 1], ahi[mt], bh[2], bh[3]);
                    MMA_BF16(acc1[mt][2 * np + 1], ahi[mt], bl[2], bl[3]);
                    MMA_BF16(acc1[mt][2 * np + 1], alo[mt], bh[2], bh[3]);
                }
            }
        }

        {
            const float* bp = (const float*)(smem + F_B1);
#pragma unroll
            for (int mt = 0; mt < 2; mt++) {
                const int m = mbase0 + mt * 16 + mo;
                const float bA = bp[m], bB = bp[m + 8];
#pragma unroll
                for (int nt = 0; nt < 4; nt++) {
                    const int n = nbase + nt * 8 + no;
                    const float v0 = fmaxf(acc1[mt][nt][0] + bA, 0.0f);
                    const float v1 = fmaxf(acc1[mt][nt][1] + bA, 0.0f);
                    const float v2 = fmaxf(acc1[mt][nt][2] + bB, 0.0f);
                    const float v3 = fmaxf(acc1[mt][nt][3] + bB, 0.0f);
                    unsigned short h, l;
                    bf16split1(v0, h, l);
                    *(unsigned short*)(smem + F_HH + n * 272 + m * 2) = h;
                    *(unsigned short*)(smem + F_HL + n * 272 + m * 2) = l;
                    bf16split1(v1, h, l);
                    *(unsigned short*)(smem + F_HH + (n + 1) * 272 + m * 2) = h;
                    *(unsigned short*)(smem + F_HL + (n + 1) * 272 + m * 2) = l;
                    bf16split1(v2, h, l);
                    *(unsigned short*)(smem + F_HH + n * 272 + (m + 8) * 2) = h;
                    *(unsigned short*)(smem + F_HL + n * 272 + (m + 8) * 2) = l;
                    bf16split1(v3, h, l);
                    *(unsigned short*)(smem + F_HH + (n + 1) * 272 + (m + 8) * 2) = h;
                    *(unsigned short*)(smem + F_HL + (n + 1) * 272 + (m + 8) * 2) = l;
                }
            }
        }
        __syncthreads();

        float acc2[2][4][4];
#pragma unroll
        for (int mt = 0; mt < 2; mt++)
#pragma unroll
            for (int nt = 0; nt < 4; nt++)
#pragma unroll
                for (int q = 0; q < 4; q++) acc2[mt][nt][q] = 0.0f;

#pragma unroll
        for (int k0 = 0; k0 < 128; k0 += 16) {
            const uint32_t ac = (uint32_t)(k0 + 8 * (lid >> 4));
            uint32_t ahi[2][4], alo[2][4];
#pragma unroll
            for (int mt = 0; mt < 2; mt++) {
                const uint32_t off = (mbase0 + mt * 16 + ar) * 272 + ac * 2;
                LDSM_X4(ahi[mt][0], ahi[mt][1], ahi[mt][2], ahi[mt][3], sb + F_W2H + off);
                LDSM_X4(alo[mt][0], alo[mt][1], alo[mt][2], alo[mt][3], sb + F_W2L + off);
            }
            const uint32_t bc = (uint32_t)(k0 + 8 * ((lid >> 3) & 1));
#pragma unroll
            for (int np = 0; np < 2; np++) {
                const uint32_t off = (nbase + np * 16 + bq) * 272 + bc * 2;
                uint32_t bh[4], bl[4];
                LDSM_X4(bh[0], bh[1], bh[2], bh[3], sb + F_HH + off);
                LDSM_X4(bl[0], bl[1], bl[2], bl[3], sb + F_HL + off);
#pragma unroll
                for (int mt = 0; mt < 2; mt++) {
                    MMA_BF16(acc2[mt][2 * np],     ahi[mt], bh[0], bh[1]);
                    MMA_BF16(acc2[mt][2 * np],     ahi[mt], bl[0], bl[1]);
                    MMA_BF16(acc2[mt][2 * np],     alo[mt], bh[0], bh[1]);
                    MMA_BF16(acc2[mt][2 * np + 1], ahi[mt], bh[2], bh[3]);
                    MMA_BF16(acc2[mt][2 * np + 1], ahi[mt], bl[2], bl[3]);
                    MMA_BF16(acc2[mt][2 * np + 1], alo[mt], bh[2], bh[3]);
                }
            }
        }
        __syncthreads();

        {
            float* Dsm = (float*)(smem + F_D);
#pragma unroll
            for (int mt = 0; mt < 2; mt++) {
                const int m = mbase0 + mt * 16 + mo;
#pragma unroll
                for (int nt = 0; nt < 4; nt++) {
                    const int n = nbase + nt * 8 + no;
                    Dsm[n * 132 + m]           = acc2[mt][nt][0];
                    Dsm[(n + 1) * 132 + m]     = acc2[mt][nt][1];
                    Dsm[n * 132 + m + 8]       = acc2[mt][nt][2];
                    Dsm[(n + 1) * 132 + m + 8] = acc2[mt][nt][3];
                }
            }
        }
        __syncthreads();

        {
            const float* Dsm = (const float*)(smem + F_D);
            const float* bp  = (const float*)(smem + F_B2);
            const int s  = tid & 127;
            const int oh = (tid >> 7) * 32;
            const long long gs = tbase + s;
            if (gs < nsamp) {
                float* op = out + gs * 128 + oh;
                const float* dp = Dsm + s * 132 + oh;
#pragma unroll
                for (int i = 0; i < 32; i += 4) {
                    float4 v = *(const float4*)(dp + i);
                    v.x += bp[oh + i];     v.y += bp[oh + i + 1];
                    v.z += bp[oh + i + 2]; v.w += bp[oh + i + 3];
                    *(float4*)(op + i) = v;
                }
            }
        }
    }
}

extern "C" void kernel_launch(void* const* d_in, const int* in_sizes, int n_in,
                              void* d_out, int out_size)
{
    const float* x   = (const float*)d_in[0];
    const float* c1w = (const float*)d_in[1];
    const float* c1b = (const float*)d_in[2];
    const float* c2w = (const float*)d_in[3];
    const float* c2b = (const float*)d_in[4];
    const float* w1  = (const float*)d_in[5];
    const float* b1  = (const float*)d_in[6];
    const float* w2  = (const float*)d_in[7];
    const float* b2  = (const float*)d_in[8];
    float* out = (float*)d_out;

    const int nsamp = in_sizes[0] / 128;

    cudaFuncSetAttribute(conv1_kernel, cudaFuncAttributeMaxDynamicSharedMemorySize, A1_SMEM);
    cudaFuncSetAttribute(head_kernel,  cudaFuncAttributeMaxDynamicSharedMemorySize, FK_SMEM);

    conv1_kernel<<<(nsamp + A1TPB - 1) / A1TPB, A1TPB, A1_SMEM>>>(x, c1w, c1b, nsamp);
    conv2_kernel<<<(nsamp + A2TPB - 1) / A2TPB, A2TPB>>>(c2w, c2b, nsamp);

    const int ntiles = (nsamp + 127) / 128;
    const int blocks = (ntiles < 148) ? ntiles : 148;
    head_kernel<<<blocks, FK_TPB, FK_SMEM>>>(w1, b1, w2, b2, out, nsamp, ntiles);
}